// round 3
// baseline (speedup 1.0000x reference)
#include <cuda_runtime.h>
#include <cstdint>

#define BB   16
#define XS_  256
#define NN   500000
#define LATD 8
#define NKX  129   // XS/2 + 1

// ---- static scratch (no allocs allowed) ----
__device__ float g_img [BB * XS_ * XS_];
__device__ float g_tmp [BB * XS_ * XS_];
__device__ float g_fre [BB * XS_ * NKX];
__device__ float g_fim [BB * XS_ * NKX];
__device__ float g_h   [BB * LATD];
__device__ float g_pose[BB * 8];

// ============================================================
// 0) zero the scatter image
// ============================================================
__global__ void k_zero() {
    int i = blockIdx.x * blockDim.x + threadIdx.x;
    if (i < BB * XS_ * XS_) g_img[i] = 0.0f;
}

// ============================================================
// 1) pose matrices + SIREN MLP h (one thread per batch element)
//    Arithmetic patterns deliberately mirror XLA: elementwise muls
//    left-associated WITHOUT fma for R; dot products as ascending
//    fma chains from 0; bias added after the dot; x30 after bias.
// ============================================================
__global__ void k_prep(const float* __restrict__ rows,
                       const float* __restrict__ shifts,
                       const float* __restrict__ latent,
                       const float* __restrict__ W0, const float* __restrict__ b0,
                       const float* __restrict__ W1, const float* __restrict__ b1,
                       const float* __restrict__ W2, const float* __restrict__ b2,
                       const float* __restrict__ W3, const float* __restrict__ b3) {
    int b = threadIdx.x;
    if (b >= BB) return;

    float rot = rows[b*3+0], tilt = rows[b*3+1], psi = rows[b*3+2];
    float ca = cosf(rot),  sa = sinf(rot);
    float cb = cosf(tilt), sb = sinf(tilt);
    float cg = cosf(psi),  sg = sinf(psi);

    float cgcb  = __fmul_rn(cg, cb);
    float nsg   = -sg;
    float nsgcb = __fmul_rn(nsg, cb);

    // Row 0 of R: [cg*cb*ca - sg*sa, cg*cb*sa + sg*ca, -cg*sb]
    float r00 = __fsub_rn(__fmul_rn(cgcb, ca), __fmul_rn(sg, sa));
    float r01 = __fadd_rn(__fmul_rn(cgcb, sa), __fmul_rn(sg, ca));
    float r02 = __fmul_rn(nsg >= -2.0f ? cg : cg, sb);  // cg*sb
    r02 = -__fmul_rn(cg, sb);
    // Row 1 of R: [-sg*cb*ca - cg*sa, -sg*cb*sa + cg*ca, sg*sb]
    float r10 = __fsub_rn(__fmul_rn(nsgcb, ca), __fmul_rn(cg, sa));
    float r11 = __fadd_rn(__fmul_rn(nsgcb, sa), __fmul_rn(cg, ca));
    float r12 = __fmul_rn(sg, sb);

    g_pose[b*8+0] = r00;
    g_pose[b*8+1] = r01;
    g_pose[b*8+2] = r02;
    g_pose[b*8+3] = r10;
    g_pose[b*8+4] = r11;
    g_pose[b*8+5] = r12;
    g_pose[b*8+6] = shifts[b*2+0];
    g_pose[b*8+7] = shifts[b*2+1];

    float lat[LATD];
    #pragma unroll
    for (int i = 0; i < LATD; i++) lat[i] = latent[b*LATD+i];

    float h[LATD], z[LATD];
    #pragma unroll
    for (int j = 0; j < LATD; j++) {
        float acc = 0.0f;
        #pragma unroll
        for (int i = 0; i < LATD; i++) acc = fmaf(lat[i], W0[i*LATD+j], acc);
        acc = __fadd_rn(acc, b0[j]);
        h[j] = sinf(__fmul_rn(30.0f, acc));
    }
    const float* Ws[3] = {W1, W2, W3};
    const float* bs[3] = {b1, b2, b3};
    for (int L = 0; L < 3; L++) {
        #pragma unroll
        for (int j = 0; j < LATD; j++) {
            float acc = 0.0f;
            #pragma unroll
            for (int i = 0; i < LATD; i++) acc = fmaf(h[i], Ws[L][i*LATD+j], acc);
            acc = __fadd_rn(acc, bs[L][j]);
            z[j] = sinf(acc);
        }
        #pragma unroll
        for (int j = 0; j < LATD; j++) h[j] = __fadd_rn(h[j], z[j]);
    }
    #pragma unroll
    for (int j = 0; j < LATD; j++) g_h[b*LATD+j] = h[j];
}

// ============================================================
// 2) rotation + decode + scatter-add (thread per point, loop over B)
// ============================================================
__global__ void __launch_bounds__(256)
k_scatter(const float* __restrict__ coords,
          const float* __restrict__ values,
          const float* __restrict__ Wd,
          const float* __restrict__ bd) {
    __shared__ float sh[BB * LATD];
    __shared__ float sp[BB * 8];
    int t = threadIdx.x;
    if (t < BB * LATD) sh[t] = g_h[t];
    if (t < BB * 8)    sp[t] = g_pose[t];
    __syncthreads();

    int n = blockIdx.x * blockDim.x + t;
    if (n >= NN) return;

    float x  = coords[3*n+0];
    float y  = coords[3*n+1];
    float zc = coords[3*n+2];
    float w[LATD];
    #pragma unroll
    for (int l = 0; l < LATD; l++) w[l] = Wd[l*NN + n];
    float vn  = values[n];
    float bdn = bd[n];

    #pragma unroll
    for (int b = 0; b < BB; b++) {
        const float* p = &sp[b*8];
        // dot as ascending fma chain from 0 (cublas/XLA pattern)
        float dx = fmaf(p[0], x, 0.0f);
        dx = fmaf(p[1], y,  dx);
        dx = fmaf(p[2], zc, dx);
        float dy = fmaf(p[3], x, 0.0f);
        dy = fmaf(p[4], y,  dy);
        dy = fmaf(p[5], zc, dy);
        // (dot + shift) + 128, each add rounded separately
        float pxf = rintf(__fadd_rn(__fadd_rn(dx, p[6]), 128.0f));
        float pyf = rintf(__fadd_rn(__fadd_rn(dy, p[7]), 128.0f));
        pxf = fminf(fmaxf(pxf, 0.0f), 255.0f);
        pyf = fminf(fmaxf(pyf, 0.0f), 255.0f);
        int px = (int)pxf;
        int py = (int)pyf;
        // delta = (h . Wd[:,n]) + bd[n];  v = values[n] + delta
        const float* hh = &sh[b*LATD];
        float acc = 0.0f;
        #pragma unroll
        for (int l = 0; l < LATD; l++) acc = fmaf(hh[l], w[l], acc);
        float v = __fadd_rn(vn, __fadd_rn(acc, bdn));
        atomicAdd(&g_img[(b*XS_ + py)*XS_ + px], v);
    }
}

// ============================================================
// 3) separable Gaussian blur (sigma=1, radius=3, zero-padded SAME)
// ============================================================
__device__ __forceinline__ float gwt(int d) {
    const float w0 = 0.00443305f;   // |d|=3
    const float w1 = 0.05400558f;   // |d|=2
    const float w2 = 0.24203623f;   // |d|=1
    const float w3 = 0.39905033f;   // d=0
    int a = d < 0 ? -d : d;
    return a == 0 ? w3 : (a == 1 ? w2 : (a == 2 ? w1 : w0));
}

__global__ void k_blur_v() {   // along y (H), g_img -> g_tmp
    int i = blockIdx.x * blockDim.x + threadIdx.x;
    if (i >= BB * XS_ * XS_) return;
    int x = i & 255;
    int y = (i >> 8) & 255;
    int b = i >> 16;
    float acc = 0.0f;
    #pragma unroll
    for (int d = -3; d <= 3; d++) {
        int yy = y + d;
        if (yy >= 0 && yy < XS_)
            acc += gwt(d) * g_img[(b*XS_ + yy)*XS_ + x];
    }
    g_tmp[i] = acc;
}

__global__ void k_blur_h() {   // along x (W), g_tmp -> g_img
    int i = blockIdx.x * blockDim.x + threadIdx.x;
    if (i >= BB * XS_ * XS_) return;
    int x = i & 255;
    float acc = 0.0f;
    #pragma unroll
    for (int d = -3; d <= 3; d++) {
        int xx = x + d;
        if (xx >= 0 && xx < XS_)
            acc += gwt(d) * g_tmp[i - x + xx];
    }
    g_img[i] = acc;
}

// ============================================================
// 256-point radix-2 DIT FFT in shared memory, 128 threads.
// Data must be loaded in bit-reversed order. sign=-1 fwd, +1 inv (unscaled).
// ============================================================
__device__ __forceinline__ void fft256(float* sre, float* sim, int t, float sign) {
    #pragma unroll
    for (int len = 2; len <= 256; len <<= 1) {
        int half = len >> 1;
        int grp = t / half;
        int j   = t - grp * half;
        int i0  = grp * len + j;
        int i1  = i0 + half;
        float a = sign * 2.0f * (float)j / (float)len;   // angle / pi
        float wr, wi;
        sincospif(a, &wi, &wr);
        float xr = sre[i1], xi = sim[i1];
        float vr = xr*wr - xi*wi;
        float vi = xr*wi + xi*wr;
        float ur = sre[i0], ui = sim[i0];
        sre[i0] = ur + vr;  sim[i0] = ui + vi;
        sre[i1] = ur - vr;  sim[i1] = ui - vi;
        __syncthreads();
    }
}

__device__ __forceinline__ int brev8(int i) { return (int)(__brev((unsigned)i) >> 24); }

// 4) row-wise rfft: g_img rows -> g_fre/g_fim [row][0..128]
__global__ void __launch_bounds__(128) k_rfft_row() {
    __shared__ float sre[256], sim[256];
    int t = threadIdx.x;
    int row = blockIdx.x;                 // b*256 + y
    const float* src = &g_img[row * XS_];
    sre[t]       = src[brev8(t)];        sim[t]       = 0.0f;
    sre[t + 128] = src[brev8(t + 128)];  sim[t + 128] = 0.0f;
    __syncthreads();
    fft256(sre, sim, t, -1.0f);
    float* dre = &g_fre[row * NKX];
    float* dim = &g_fim[row * NKX];
    dre[t] = sre[t];  dim[t] = sim[t];
    if (t == 0) { dre[128] = sre[128]; dim[128] = sim[128]; }
}

// 5) column FFT over y, multiply by CTF, inverse column FFT (fused)
__global__ void __launch_bounds__(128) k_col_ctf(const float* __restrict__ ctf) {
    __shared__ float sre[256], sim[256];
    int t  = threadIdx.x;
    int b  = blockIdx.x / NKX;
    int kx = blockIdx.x % NKX;
    int base = b * XS_ * NKX + kx;

    int r0 = brev8(t), r1 = brev8(t + 128);
    sre[t]       = g_fre[base + r0 * NKX];  sim[t]       = g_fim[base + r0 * NKX];
    sre[t + 128] = g_fre[base + r1 * NKX];  sim[t + 128] = g_fim[base + r1 * NKX];
    __syncthreads();
    fft256(sre, sim, t, -1.0f);

    // multiply by real CTF at (b, ky, kx), then re-bit-reverse for inverse pass
    const float* cp = &ctf[base];
    float c0 = cp[t * NKX];
    float c1 = cp[(t + 128) * NKX];
    float ar = sre[t]       * c0, ai = sim[t]       * c0;
    float br = sre[t + 128] * c1, bi = sim[t + 128] * c1;
    __syncthreads();
    sre[r0] = ar;  sim[r0] = ai;
    sre[r1] = br;  sim[r1] = bi;
    __syncthreads();
    fft256(sre, sim, t, 1.0f);            // unscaled inverse

    g_fre[base + t * NKX]         = sre[t];
    g_fim[base + t * NKX]         = sim[t];
    g_fre[base + (t + 128) * NKX] = sre[t + 128];
    g_fim[base + (t + 128) * NKX] = sim[t + 128];
}

// 6) row-wise inverse rfft (Hermitian reconstruct) -> d_out, scale 1/65536
__global__ void __launch_bounds__(128) k_irfft_row(float* __restrict__ out) {
    __shared__ float sre[256], sim[256];
    int t = threadIdx.x;
    int row = blockIdx.x;                 // b*256 + y
    const float* dre = &g_fre[row * NKX];
    const float* dim = &g_fim[row * NKX];
    #pragma unroll
    for (int i = t; i < 256; i += 128) {
        int k = brev8(i);
        float re, im;
        if (k <= 128) { re = dre[k];        im =  dim[k]; }
        else          { re = dre[256 - k];  im = -dim[256 - k]; }
        sre[i] = re;  sim[i] = im;
    }
    __syncthreads();
    fft256(sre, sim, t, 1.0f);
    const float s = 1.0f / 65536.0f;      // 1/(256*256)
    out[row * XS_ + t]       = sre[t]       * s;
    out[row * XS_ + t + 128] = sre[t + 128] * s;
}

// ============================================================
extern "C" void kernel_launch(void* const* d_in, const int* in_sizes, int n_in,
                              void* d_out, int out_size) {
    const float* rows   = (const float*)d_in[0];
    const float* shifts = (const float*)d_in[1];
    const float* latent = (const float*)d_in[2];
    const float* coords = (const float*)d_in[3];
    const float* values = (const float*)d_in[4];
    const float* W0     = (const float*)d_in[5];
    const float* b0     = (const float*)d_in[6];
    const float* W1     = (const float*)d_in[7];
    const float* b1     = (const float*)d_in[8];
    const float* W2     = (const float*)d_in[9];
    const float* b2     = (const float*)d_in[10];
    const float* W3     = (const float*)d_in[11];
    const float* b3     = (const float*)d_in[12];
    const float* Wd     = (const float*)d_in[13];
    const float* bd     = (const float*)d_in[14];
    const float* ctf    = (const float*)d_in[15];
    float* out = (float*)d_out;

    const int IMG = BB * XS_ * XS_;
    k_zero<<<(IMG + 255) / 256, 256>>>();
    k_prep<<<1, 16>>>(rows, shifts, latent, W0, b0, W1, b1, W2, b2, W3, b3);
    k_scatter<<<(NN + 255) / 256, 256>>>(coords, values, Wd, bd);
    k_blur_v<<<(IMG + 255) / 256, 256>>>();
    k_blur_h<<<(IMG + 255) / 256, 256>>>();
    k_rfft_row<<<BB * XS_, 128>>>();
    k_col_ctf<<<BB * NKX, 128>>>(ctf);
    k_irfft_row<<<BB * XS_, 128>>>(out);
}